// round 10
// baseline (speedup 1.0000x reference)
#include <cuda_runtime.h>
#include <math.h>

#define N_NODES 100000
#define D 128
#define E_MAX 2000000
#define SCAN_T 1024
#define SCAN_B ((N_NODES + SCAN_T - 1) / SCAN_T)   // 98

// Scratch (device globals: allocation-free per harness rules)
__device__ float g_sum[(size_t)N_NODES * D];   // mean-aggregated features
__device__ float g_h[(size_t)N_NODES * D];     // layer-1 activations
__device__ int   g_off[N_NODES + 1];           // CSR row offsets (by dst)
__device__ int   g_cur[N_NODES];               // degree counts / fill cursors
__device__ int   g_src[E_MAX];                 // CSR column (src) ids
__device__ int   g_part[SCAN_B];               // per-block scan partials
__device__ int   g_is64;                       // 1 if edge_index is int64

// ---- packed f32x2 helpers (sm_103a FFMA2) ----------------------------------
__device__ __forceinline__ unsigned long long pack_dup(float a) {
    unsigned long long r;
    asm("mov.b64 %0, {%1, %1};" : "=l"(r) : "f"(a));
    return r;
}
__device__ __forceinline__ void fma2(unsigned long long& d,
                                     unsigned long long a,
                                     unsigned long long b) {
    asm("fma.rn.f32x2 %0, %1, %2, %0;" : "+l"(d) : "l"(a), "l"(b));
}
__device__ __forceinline__ float2 unpack2(unsigned long long v) {
    float lo, hi;
    asm("mov.b64 {%0, %1}, %2;" : "=f"(lo), "=f"(hi) : "l"(v));
    return make_float2(lo, hi);
}

// ---------------------------------------------------------------------------
// Probe edge-index width: int64 indices < 100000 have zero high words.
// ---------------------------------------------------------------------------
__global__ void detect_kernel(const int* __restrict__ ei) {
    int v = ei[2 * threadIdx.x + 1];
    int nz = __syncthreads_or(v != 0);
    if (threadIdx.x == 0) g_is64 = nz ? 0 : 1;
}

__global__ void zero_deg_kernel() {
    int i = blockIdx.x * blockDim.x + threadIdx.x;
    if (i < N_NODES) g_cur[i] = 0;
}

__global__ void hist_kernel(const int* __restrict__ ei, int E) {
    int i = blockIdx.x * blockDim.x + threadIdx.x;
    if (i >= E) return;
    int d = g_is64 ? ei[2 * ((size_t)E + i)] : ei[(size_t)E + i];
    atomicAdd(&g_cur[d], 1);
}

// ---- 3-phase multi-block exclusive scan of g_cur -> g_off (+fill cursors) ----

__global__ void __launch_bounds__(SCAN_T)
scan_partial_kernel() {
    int i = blockIdx.x * SCAN_T + threadIdx.x;
    int v = (i < N_NODES) ? g_cur[i] : 0;
    int lane = threadIdx.x & 31, wid = threadIdx.x >> 5;
    #pragma unroll
    for (int o = 16; o; o >>= 1) v += __shfl_down_sync(0xffffffffu, v, o);
    __shared__ int ws[32];
    if (lane == 0) ws[wid] = v;
    __syncthreads();
    if (wid == 0) {
        int t = ws[lane];
        #pragma unroll
        for (int o = 16; o; o >>= 1) t += __shfl_down_sync(0xffffffffu, t, o);
        if (lane == 0) g_part[blockIdx.x] = t;
    }
}

__global__ void scan_part2_kernel(int E) {
    __shared__ int s[128];
    int tid = threadIdx.x;
    int v = (tid < SCAN_B) ? g_part[tid] : 0;
    s[tid] = v;
    __syncthreads();
    for (int o = 1; o < 128; o <<= 1) {
        int t = (tid >= o) ? s[tid - o] : 0;
        __syncthreads();
        s[tid] += t;
        __syncthreads();
    }
    if (tid < SCAN_B) g_part[tid] = s[tid] - v;   // exclusive prefix
    if (tid == 0) g_off[N_NODES] = E;
}

__global__ void __launch_bounds__(SCAN_T)
scan_final_kernel() {
    int i = blockIdx.x * SCAN_T + threadIdx.x;
    int v = (i < N_NODES) ? g_cur[i] : 0;
    int lane = threadIdx.x & 31, wid = threadIdx.x >> 5;

    int inc = v;
    #pragma unroll
    for (int o = 1; o < 32; o <<= 1) {
        int t = __shfl_up_sync(0xffffffffu, inc, o);
        if (lane >= o) inc += t;
    }
    __shared__ int ws[32], wo[32];
    if (lane == 31) ws[wid] = inc;
    __syncthreads();
    if (wid == 0) {
        int t = ws[lane];
        int ts = t;
        #pragma unroll
        for (int o = 1; o < 32; o <<= 1) {
            int u = __shfl_up_sync(0xffffffffu, ts, o);
            if (lane >= o) ts += u;
        }
        wo[lane] = ts - t;
    }
    __syncthreads();
    int pre = g_part[blockIdx.x] + wo[wid] + (inc - v);
    if (i < N_NODES) { g_off[i] = pre; g_cur[i] = pre; }
}

__global__ void fill_kernel(const int* __restrict__ ei, int E) {
    int i = blockIdx.x * blockDim.x + threadIdx.x;
    if (i >= E) return;
    int s, d;
    if (g_is64) {
        s = ei[2 * (size_t)i];
        d = ei[2 * ((size_t)E + i)];
    } else {
        s = ei[i];
        d = ei[(size_t)E + i];
    }
    int pos = atomicAdd(&g_cur[d], 1);
    g_src[pos] = s;
}

// ---------------------------------------------------------------------------
// Aggregation: one warp per dst node, register accumulation, writes the MEAN.
// ---------------------------------------------------------------------------
__global__ void __launch_bounds__(256)
agg_kernel(const float* __restrict__ feat) {
    const int w    = (int)((blockIdx.x * (size_t)blockDim.x + threadIdx.x) >> 5);
    const int lane = threadIdx.x & 31;
    if (w >= N_NODES) return;

    const int beg = g_off[w], end = g_off[w + 1];
    const int j0 = lane * 4;

    float4 a0 = make_float4(0.f, 0.f, 0.f, 0.f);
    float4 a1 = a0, a2 = a0, a3 = a0;

    int e = beg;
    for (; e + 3 < end; e += 4) {
        int s0 = g_src[e], s1 = g_src[e + 1], s2 = g_src[e + 2], s3 = g_src[e + 3];
        float4 v0 = *reinterpret_cast<const float4*>(feat + (size_t)s0 * D + j0);
        float4 v1 = *reinterpret_cast<const float4*>(feat + (size_t)s1 * D + j0);
        float4 v2 = *reinterpret_cast<const float4*>(feat + (size_t)s2 * D + j0);
        float4 v3 = *reinterpret_cast<const float4*>(feat + (size_t)s3 * D + j0);
        a0.x += v0.x; a0.y += v0.y; a0.z += v0.z; a0.w += v0.w;
        a1.x += v1.x; a1.y += v1.y; a1.z += v1.z; a1.w += v1.w;
        a2.x += v2.x; a2.y += v2.y; a2.z += v2.z; a2.w += v2.w;
        a3.x += v3.x; a3.y += v3.y; a3.z += v3.z; a3.w += v3.w;
    }
    for (; e < end; e++) {
        int s0 = g_src[e];
        float4 v0 = *reinterpret_cast<const float4*>(feat + (size_t)s0 * D + j0);
        a0.x += v0.x; a0.y += v0.y; a0.z += v0.z; a0.w += v0.w;
    }

    float rc = 1.0f / fmaxf((float)(end - beg), 1.0f);
    float4 r;
    r.x = (a0.x + a1.x + a2.x + a3.x) * rc;
    r.y = (a0.y + a1.y + a2.y + a3.y) * rc;
    r.z = (a0.z + a1.z + a2.z + a3.z) * rc;
    r.w = (a0.w + a1.w + a2.w + a3.w) * rc;
    *reinterpret_cast<float4*>(g_sum + (size_t)w * D + j0) = r;
}

// ---------------------------------------------------------------------------
// Fused SAGE layer, f32x2 FFMA2 node-pair packing, TWO-PASS staging:
//   pass 1: stage agg pairs -> accumulate Wl; pass 2: restage x pairs -> Wr.
// Staging halves to 4KB/warp so 16 warps (512 thr) fit alongside 128KB weights
// -> 4 warps/SMSP for latency hiding. acc f32x2 = (out_j_n0, out_j_n1);
// multiplier = activation pair (LDS broadcast, no MOV); weight dup'd once per
// (j,k), reused by 4 node-pairs.
// ---------------------------------------------------------------------------
#define SAGE_T 512
#define SAGE_W (SAGE_T / 32)           // 16 warps
// smem floats: wl 16384 | wr 16384 | bias 128 | staging 16*1024
#define SAGE_SMEM_FLOATS (16384 + 16384 + 128 + SAGE_W * 1024)

// One 4k-step block of FFMA2s against weight matrix `w` using staged pairs
// `st` ([4 pairs][256] pair-interleaved).
__device__ __forceinline__ void mm_block(const float* __restrict__ w,
                                         const float* __restrict__ st,
                                         unsigned long long (&acc)[4][4],
                                         int k, int j0) {
    unsigned long long wd[4][4];
    #pragma unroll
    for (int kk = 0; kk < 4; kk++) {
        float4 wv = *reinterpret_cast<const float4*>(w + (k + kk) * 128 + j0);
        wd[kk][0] = pack_dup(wv.x); wd[kk][1] = pack_dup(wv.y);
        wd[kk][2] = pack_dup(wv.z); wd[kk][3] = pack_dup(wv.w);
    }
    #pragma unroll
    for (int p = 0; p < 4; p++) {
        ulonglong2 a01 = *reinterpret_cast<const ulonglong2*>(st + p * 256 + 2 * k);
        ulonglong2 a23 = *reinterpret_cast<const ulonglong2*>(st + p * 256 + 2 * k + 4);
        #pragma unroll
        for (int j = 0; j < 4; j++) {
            fma2(acc[j][p], a01.x, wd[0][j]);
            fma2(acc[j][p], a01.y, wd[1][j]);
            fma2(acc[j][p], a23.x, wd[2][j]);
            fma2(acc[j][p], a23.y, wd[3][j]);
        }
    }
}

template <bool NORM_RELU>
__global__ void __launch_bounds__(SAGE_T, 1)
sage_kernel(const float* __restrict__ xin,
            const float* __restrict__ Wl,
            const float* __restrict__ b,
            const float* __restrict__ Wr,
            float* __restrict__ out) {
    extern __shared__ float sm[];
    float* wl    = sm;               // [128][128] : wl[k*128+j] = Wl[j][k]
    float* wr    = sm + 16384;
    float* bs    = sm + 32768;       // [128]
    float* stage = sm + 32896;       // [16 warps][1024]

    const int tid = threadIdx.x;

    for (int i = tid; i < 16384; i += SAGE_T) {
        int k = i >> 7, j = i & 127;
        wl[i] = Wl[j * 128 + k];
        wr[i] = Wr[j * 128 + k];
    }
    for (int i = tid; i < 128; i += SAGE_T) bs[i] = b[i];
    __syncthreads();

    const int lane = tid & 31;
    const int wib  = tid >> 5;
    const int gw   = blockIdx.x * SAGE_W + wib;
    const int nw   = gridDim.x * SAGE_W;
    float* st      = stage + wib * 1024;   // [4 pairs][128k][2] one buffer
    const int j0   = lane * 4;

    for (int g = gw; g < N_NODES / 8; g += nw) {
        const int base = g * 8;

        // ---- accumulators: acc[j][p] = (out_{j0+j} of n0(p), of n1(p))
        unsigned long long acc[4][4];
        {
            float4 bv = *reinterpret_cast<const float4*>(bs + j0);
            unsigned long long b0 = pack_dup(bv.x), b1 = pack_dup(bv.y);
            unsigned long long b2 = pack_dup(bv.z), b3 = pack_dup(bv.w);
            #pragma unroll
            for (int p = 0; p < 4; p++) {
                acc[0][p] = b0; acc[1][p] = b1; acc[2][p] = b2; acc[3][p] = b3;
            }
        }

        // ======== pass 1: agg pairs vs Wl ========
        #pragma unroll
        for (int p = 0; p < 4; p++) {
            const int n0 = base + 2 * p, n1 = n0 + 1;
            float4 s0 = *reinterpret_cast<const float4*>(g_sum + (size_t)n0 * D + j0);
            float4 s1 = *reinterpret_cast<const float4*>(g_sum + (size_t)n1 * D + j0);
            float* dA = st + p * 256 + 8 * lane;
            *reinterpret_cast<float4*>(dA)     = make_float4(s0.x, s1.x, s0.y, s1.y);
            *reinterpret_cast<float4*>(dA + 4) = make_float4(s0.z, s1.z, s0.w, s1.w);
        }
        __syncwarp();
        #pragma unroll 1
        for (int k = 0; k < 128; k += 4) mm_block(wl, st, acc, k, j0);
        __syncwarp();

        // ======== pass 2: x pairs vs Wr (restage same buffer) ========
        #pragma unroll
        for (int p = 0; p < 4; p++) {
            const int n0 = base + 2 * p, n1 = n0 + 1;
            float4 x0 = *reinterpret_cast<const float4*>(xin + (size_t)n0 * D + j0);
            float4 x1 = *reinterpret_cast<const float4*>(xin + (size_t)n1 * D + j0);
            float* dX = st + p * 256 + 8 * lane;
            *reinterpret_cast<float4*>(dX)     = make_float4(x0.x, x1.x, x0.y, x1.y);
            *reinterpret_cast<float4*>(dX + 4) = make_float4(x0.z, x1.z, x0.w, x1.w);
        }
        __syncwarp();
        #pragma unroll 1
        for (int k = 0; k < 128; k += 4) mm_block(wr, st, acc, k, j0);
        __syncwarp();

        // ---- epilogue: per pair, unpack, (normalize+relu), store
        #pragma unroll
        for (int p = 0; p < 4; p++) {
            float2 v0 = unpack2(acc[0][p]);
            float2 v1 = unpack2(acc[1][p]);
            float2 v2 = unpack2(acc[2][p]);
            float2 v3 = unpack2(acc[3][p]);
            float4 o0 = make_float4(v0.x, v1.x, v2.x, v3.x);   // node base+2p
            float4 o1 = make_float4(v0.y, v1.y, v2.y, v3.y);   // node base+2p+1
            if (NORM_RELU) {
                float s0 = o0.x * o0.x + o0.y * o0.y + o0.z * o0.z + o0.w * o0.w;
                float s1 = o1.x * o1.x + o1.y * o1.y + o1.z * o1.z + o1.w * o1.w;
                #pragma unroll
                for (int o = 16; o; o >>= 1) {
                    s0 += __shfl_xor_sync(0xffffffffu, s0, o);
                    s1 += __shfl_xor_sync(0xffffffffu, s1, o);
                }
                float i0 = 1.0f / fmaxf(sqrtf(s0), 1e-12f);
                float i1 = 1.0f / fmaxf(sqrtf(s1), 1e-12f);
                o0.x = fmaxf(o0.x * i0, 0.f); o0.y = fmaxf(o0.y * i0, 0.f);
                o0.z = fmaxf(o0.z * i0, 0.f); o0.w = fmaxf(o0.w * i0, 0.f);
                o1.x = fmaxf(o1.x * i1, 0.f); o1.y = fmaxf(o1.y * i1, 0.f);
                o1.z = fmaxf(o1.z * i1, 0.f); o1.w = fmaxf(o1.w * i1, 0.f);
            }
            *reinterpret_cast<float4*>(out + (size_t)(base + 2 * p)     * D + j0) = o0;
            *reinterpret_cast<float4*>(out + (size_t)(base + 2 * p + 1) * D + j0) = o1;
        }
    }
}

// ---------------------------------------------------------------------------
extern "C" void kernel_launch(void* const* d_in, const int* in_sizes, int n_in,
                              void* d_out, int out_size) {
    const float* x   = (const float*)d_in[0];
    const int*   ei  = (const int*)d_in[1];
    const float* W1l = (const float*)d_in[2];
    const float* b1  = (const float*)d_in[3];
    const float* W1r = (const float*)d_in[4];
    const float* W2l = (const float*)d_in[5];
    const float* b2  = (const float*)d_in[6];
    const float* W2r = (const float*)d_in[7];
    float*       out = (float*)d_out;

    const int E = in_sizes[1] / 2;

    float* hbuf = nullptr;
    cudaGetSymbolAddress((void**)&hbuf, g_h);

    int sms = 148;
    cudaDeviceGetAttribute(&sms, cudaDevAttrMultiProcessorCount, 0);

    const int smem_bytes = SAGE_SMEM_FLOATS * (int)sizeof(float);   // 197,120 B
    cudaFuncSetAttribute(sage_kernel<true>,  cudaFuncAttributeMaxDynamicSharedMemorySize, smem_bytes);
    cudaFuncSetAttribute(sage_kernel<false>, cudaFuncAttributeMaxDynamicSharedMemorySize, smem_bytes);

    const int eb = (E + 255) / 256;
    const int ab = (N_NODES + 7) / 8;

    // ---- CSR build (once per launch) ----
    detect_kernel<<<1, 1024>>>(ei);
    zero_deg_kernel<<<(N_NODES + 255) / 256, 256>>>();
    hist_kernel<<<eb, 256>>>(ei, E);
    scan_partial_kernel<<<SCAN_B, SCAN_T>>>();
    scan_part2_kernel<<<1, 128>>>(E);
    scan_final_kernel<<<SCAN_B, SCAN_T>>>();
    fill_kernel<<<eb, 256>>>(ei, E);

    // ---- Layer 1 ----
    agg_kernel<<<ab, 256>>>(x);
    sage_kernel<true><<<sms, SAGE_T, smem_bytes>>>(x, W1l, b1, W1r, hbuf);

    // ---- Layer 2 ----
    agg_kernel<<<ab, 256>>>(hbuf);
    sage_kernel<false><<<sms, SAGE_T, smem_bytes>>>(hbuf, W2l, b2, W2r, out);
}

// round 11
// speedup vs baseline: 1.0808x; 1.0808x over previous
#include <cuda_runtime.h>
#include <math.h>

#define N_NODES 100000
#define D 128
#define E_MAX 2000000
#define SCAN_T 1024
#define SCAN_B ((N_NODES + SCAN_T - 1) / SCAN_T)   // 98

// Scratch (device globals: allocation-free per harness rules)
__device__ float g_sum[(size_t)N_NODES * D];   // mean-aggregated features
__device__ float g_h[(size_t)N_NODES * D];     // layer-1 activations
__device__ int   g_off[N_NODES + 1];           // CSR row offsets (by dst)
__device__ int   g_cur[N_NODES];               // degree counts / fill cursors
__device__ int   g_src[E_MAX];                 // CSR column (src) ids
__device__ int   g_part[SCAN_B];               // per-block scan partials
__device__ int   g_is64;                       // 1 if edge_index is int64

// ---- packed f32x2 helpers (sm_103a FFMA2) ----------------------------------
__device__ __forceinline__ unsigned long long pack_dup(float a) {
    unsigned long long r;
    asm("mov.b64 %0, {%1, %1};" : "=l"(r) : "f"(a));
    return r;
}
__device__ __forceinline__ void fma2(unsigned long long& d,
                                     unsigned long long a,
                                     unsigned long long b) {
    asm("fma.rn.f32x2 %0, %1, %2, %0;" : "+l"(d) : "l"(a), "l"(b));
}
__device__ __forceinline__ float2 unpack2(unsigned long long v) {
    float lo, hi;
    asm("mov.b64 {%0, %1}, %2;" : "=f"(lo), "=f"(hi) : "l"(v));
    return make_float2(lo, hi);
}

// ---------------------------------------------------------------------------
// Probe edge-index width: int64 indices < 100000 have zero high words.
// ---------------------------------------------------------------------------
__global__ void detect_kernel(const int* __restrict__ ei) {
    int v = ei[2 * threadIdx.x + 1];
    int nz = __syncthreads_or(v != 0);
    if (threadIdx.x == 0) g_is64 = nz ? 0 : 1;
}

__global__ void zero_deg_kernel() {
    int i = blockIdx.x * blockDim.x + threadIdx.x;
    if (i < N_NODES) g_cur[i] = 0;
}

__global__ void hist_kernel(const int* __restrict__ ei, int E) {
    int i = blockIdx.x * blockDim.x + threadIdx.x;
    if (i >= E) return;
    int d = g_is64 ? ei[2 * ((size_t)E + i)] : ei[(size_t)E + i];
    atomicAdd(&g_cur[d], 1);
}

// ---- 3-phase multi-block exclusive scan of g_cur -> g_off (+fill cursors) ----

__global__ void __launch_bounds__(SCAN_T)
scan_partial_kernel() {
    int i = blockIdx.x * SCAN_T + threadIdx.x;
    int v = (i < N_NODES) ? g_cur[i] : 0;
    int lane = threadIdx.x & 31, wid = threadIdx.x >> 5;
    #pragma unroll
    for (int o = 16; o; o >>= 1) v += __shfl_down_sync(0xffffffffu, v, o);
    __shared__ int ws[32];
    if (lane == 0) ws[wid] = v;
    __syncthreads();
    if (wid == 0) {
        int t = ws[lane];
        #pragma unroll
        for (int o = 16; o; o >>= 1) t += __shfl_down_sync(0xffffffffu, t, o);
        if (lane == 0) g_part[blockIdx.x] = t;
    }
}

__global__ void scan_part2_kernel(int E) {
    __shared__ int s[128];
    int tid = threadIdx.x;
    int v = (tid < SCAN_B) ? g_part[tid] : 0;
    s[tid] = v;
    __syncthreads();
    for (int o = 1; o < 128; o <<= 1) {
        int t = (tid >= o) ? s[tid - o] : 0;
        __syncthreads();
        s[tid] += t;
        __syncthreads();
    }
    if (tid < SCAN_B) g_part[tid] = s[tid] - v;   // exclusive prefix
    if (tid == 0) g_off[N_NODES] = E;
}

__global__ void __launch_bounds__(SCAN_T)
scan_final_kernel() {
    int i = blockIdx.x * SCAN_T + threadIdx.x;
    int v = (i < N_NODES) ? g_cur[i] : 0;
    int lane = threadIdx.x & 31, wid = threadIdx.x >> 5;

    int inc = v;
    #pragma unroll
    for (int o = 1; o < 32; o <<= 1) {
        int t = __shfl_up_sync(0xffffffffu, inc, o);
        if (lane >= o) inc += t;
    }
    __shared__ int ws[32], wo[32];
    if (lane == 31) ws[wid] = inc;
    __syncthreads();
    if (wid == 0) {
        int t = ws[lane];
        int ts = t;
        #pragma unroll
        for (int o = 1; o < 32; o <<= 1) {
            int u = __shfl_up_sync(0xffffffffu, ts, o);
            if (lane >= o) ts += u;
        }
        wo[lane] = ts - t;
    }
    __syncthreads();
    int pre = g_part[blockIdx.x] + wo[wid] + (inc - v);
    if (i < N_NODES) { g_off[i] = pre; g_cur[i] = pre; }
}

__global__ void fill_kernel(const int* __restrict__ ei, int E) {
    int i = blockIdx.x * blockDim.x + threadIdx.x;
    if (i >= E) return;
    int s, d;
    if (g_is64) {
        s = ei[2 * (size_t)i];
        d = ei[2 * ((size_t)E + i)];
    } else {
        s = ei[i];
        d = ei[(size_t)E + i];
    }
    int pos = atomicAdd(&g_cur[d], 1);
    g_src[pos] = s;
}

// ---------------------------------------------------------------------------
// Aggregation: one warp per dst node, register accumulation, writes the MEAN.
// ---------------------------------------------------------------------------
__global__ void __launch_bounds__(256)
agg_kernel(const float* __restrict__ feat) {
    const int w    = (int)((blockIdx.x * (size_t)blockDim.x + threadIdx.x) >> 5);
    const int lane = threadIdx.x & 31;
    if (w >= N_NODES) return;

    const int beg = g_off[w], end = g_off[w + 1];
    const int j0 = lane * 4;

    float4 a0 = make_float4(0.f, 0.f, 0.f, 0.f);
    float4 a1 = a0, a2 = a0, a3 = a0;

    int e = beg;
    for (; e + 3 < end; e += 4) {
        int s0 = g_src[e], s1 = g_src[e + 1], s2 = g_src[e + 2], s3 = g_src[e + 3];
        float4 v0 = *reinterpret_cast<const float4*>(feat + (size_t)s0 * D + j0);
        float4 v1 = *reinterpret_cast<const float4*>(feat + (size_t)s1 * D + j0);
        float4 v2 = *reinterpret_cast<const float4*>(feat + (size_t)s2 * D + j0);
        float4 v3 = *reinterpret_cast<const float4*>(feat + (size_t)s3 * D + j0);
        a0.x += v0.x; a0.y += v0.y; a0.z += v0.z; a0.w += v0.w;
        a1.x += v1.x; a1.y += v1.y; a1.z += v1.z; a1.w += v1.w;
        a2.x += v2.x; a2.y += v2.y; a2.z += v2.z; a2.w += v2.w;
        a3.x += v3.x; a3.y += v3.y; a3.z += v3.z; a3.w += v3.w;
    }
    for (; e < end; e++) {
        int s0 = g_src[e];
        float4 v0 = *reinterpret_cast<const float4*>(feat + (size_t)s0 * D + j0);
        a0.x += v0.x; a0.y += v0.y; a0.z += v0.z; a0.w += v0.w;
    }

    float rc = 1.0f / fmaxf((float)(end - beg), 1.0f);
    float4 r;
    r.x = (a0.x + a1.x + a2.x + a3.x) * rc;
    r.y = (a0.y + a1.y + a2.y + a3.y) * rc;
    r.z = (a0.z + a1.z + a2.z + a3.z) * rc;
    r.w = (a0.w + a1.w + a2.w + a3.w) * rc;
    *reinterpret_cast<float4*>(g_sum + (size_t)w * D + j0) = r;
}

// ---------------------------------------------------------------------------
// Fused SAGE layer, f32x2 FFMA2 node-pair packing + SOFTWARE-PIPELINED LDGs:
//   acc f32x2 = (out_j of n0, out_j of n1); multiplier = activation pair from
//   pair-interleaved smem (LDS broadcast, no MOV); weight dup'd once per (j,k),
//   reused by 4 node-pairs. 12 warps, 8KB staging/warp (R9 config).
// Pipelining: X LDGs issue BEFORE the Wl k-loop; next group's A LDGs issue
// before the Wr k-loop — every LDG batch is covered by a full k-loop.
// ---------------------------------------------------------------------------
#define SAGE_T 384
#define SAGE_W (SAGE_T / 32)           // 12 warps
// smem floats: wl 16384 | wr 16384 | bias 128 | staging 12*2048
#define SAGE_SMEM_FLOATS (16384 + 16384 + 128 + SAGE_W * 2048)

// Load one group's 4 node-pairs from `src`, pre-interleaved into 8 float4s.
__device__ __forceinline__ void ldg_pairs(const float* __restrict__ src,
                                          int base, int j0, float4 (&r)[8]) {
    #pragma unroll
    for (int p = 0; p < 4; p++) {
        const int n0 = base + 2 * p, n1 = n0 + 1;
        float4 v0 = *reinterpret_cast<const float4*>(src + (size_t)n0 * D + j0);
        float4 v1 = *reinterpret_cast<const float4*>(src + (size_t)n1 * D + j0);
        r[2 * p]     = make_float4(v0.x, v1.x, v0.y, v1.y);
        r[2 * p + 1] = make_float4(v0.z, v1.z, v0.w, v1.w);
    }
}

// Store pre-interleaved regs to staging.
__device__ __forceinline__ void sts_pairs(float* __restrict__ st,
                                          int lane, const float4 (&r)[8]) {
    #pragma unroll
    for (int p = 0; p < 4; p++) {
        float* d = st + p * 256 + 8 * lane;
        *reinterpret_cast<float4*>(d)     = r[2 * p];
        *reinterpret_cast<float4*>(d + 4) = r[2 * p + 1];
    }
}

// One 4k-step block of FFMA2s against weight matrix `w` using staged pairs.
__device__ __forceinline__ void mm_block(const float* __restrict__ w,
                                         const float* __restrict__ st,
                                         unsigned long long (&acc)[4][4],
                                         int k, int j0) {
    unsigned long long wd[4][4];
    #pragma unroll
    for (int kk = 0; kk < 4; kk++) {
        float4 wv = *reinterpret_cast<const float4*>(w + (k + kk) * 128 + j0);
        wd[kk][0] = pack_dup(wv.x); wd[kk][1] = pack_dup(wv.y);
        wd[kk][2] = pack_dup(wv.z); wd[kk][3] = pack_dup(wv.w);
    }
    #pragma unroll
    for (int p = 0; p < 4; p++) {
        ulonglong2 a01 = *reinterpret_cast<const ulonglong2*>(st + p * 256 + 2 * k);
        ulonglong2 a23 = *reinterpret_cast<const ulonglong2*>(st + p * 256 + 2 * k + 4);
        #pragma unroll
        for (int j = 0; j < 4; j++) {
            fma2(acc[j][p], a01.x, wd[0][j]);
            fma2(acc[j][p], a01.y, wd[1][j]);
            fma2(acc[j][p], a23.x, wd[2][j]);
            fma2(acc[j][p], a23.y, wd[3][j]);
        }
    }
}

template <bool NORM_RELU>
__global__ void __launch_bounds__(SAGE_T, 1)
sage_kernel(const float* __restrict__ xin,
            const float* __restrict__ Wl,
            const float* __restrict__ b,
            const float* __restrict__ Wr,
            float* __restrict__ out) {
    extern __shared__ float sm[];
    float* wl    = sm;               // [128][128] : wl[k*128+j] = Wl[j][k]
    float* wr    = sm + 16384;
    float* bs    = sm + 32768;       // [128]
    float* stage = sm + 32896;       // [12 warps][2048]

    const int tid = threadIdx.x;

    for (int i = tid; i < 16384; i += SAGE_T) {
        int k = i >> 7, j = i & 127;
        wl[i] = Wl[j * 128 + k];
        wr[i] = Wr[j * 128 + k];
    }
    for (int i = tid; i < 128; i += SAGE_T) bs[i] = b[i];
    __syncthreads();

    const int lane = tid & 31;
    const int wib  = tid >> 5;
    const int gw   = blockIdx.x * SAGE_W + wib;
    const int nw   = gridDim.x * SAGE_W;
    float* stA     = stage + wib * 2048;   // agg pairs [4p][256]
    float* stX     = stA + 1024;           // x pairs
    const int j0   = lane * 4;
    const int GLIM = N_NODES / 8;          // 12500

    if (gw >= GLIM) return;

    float4 rA[8];
    ldg_pairs(g_sum, gw * 8, j0, rA);      // prologue: first group's A

    for (int g = gw; g < GLIM; g += nw) {
        const int base = g * 8;

        // commit A staging (LDGs issued one k-loop ago, or in prologue)
        sts_pairs(stA, lane, rA);
        __syncwarp();

        // issue X LDGs now — hidden by the Wl k-loop below
        float4 rX[8];
        ldg_pairs(xin, base, j0, rX);

        // accumulators (bias init)
        unsigned long long acc[4][4];
        {
            float4 bv = *reinterpret_cast<const float4*>(bs + j0);
            unsigned long long b0 = pack_dup(bv.x), b1 = pack_dup(bv.y);
            unsigned long long b2 = pack_dup(bv.z), b3 = pack_dup(bv.w);
            #pragma unroll
            for (int p = 0; p < 4; p++) {
                acc[0][p] = b0; acc[1][p] = b1; acc[2][p] = b2; acc[3][p] = b3;
            }
        }

        // ---- Wl pass over staged A pairs
        #pragma unroll 1
        for (int k = 0; k < 128; k += 4) mm_block(wl, stA, acc, k, j0);

        // commit X staging (latency covered by Wl pass)
        sts_pairs(stX, lane, rX);
        __syncwarp();

        // issue next group's A LDGs — hidden by the Wr k-loop below
        const int gn = g + nw;
        if (gn < GLIM) ldg_pairs(g_sum, gn * 8, j0, rA);

        // ---- Wr pass over staged X pairs
        #pragma unroll 1
        for (int k = 0; k < 128; k += 4) mm_block(wr, stX, acc, k, j0);
        __syncwarp();

        // ---- epilogue: per pair, unpack, (normalize+relu), store
        #pragma unroll
        for (int p = 0; p < 4; p++) {
            float2 v0 = unpack2(acc[0][p]);
            float2 v1 = unpack2(acc[1][p]);
            float2 v2 = unpack2(acc[2][p]);
            float2 v3 = unpack2(acc[3][p]);
            float4 o0 = make_float4(v0.x, v1.x, v2.x, v3.x);   // node base+2p
            float4 o1 = make_float4(v0.y, v1.y, v2.y, v3.y);   // node base+2p+1
            if (NORM_RELU) {
                float s0 = o0.x * o0.x + o0.y * o0.y + o0.z * o0.z + o0.w * o0.w;
                float s1 = o1.x * o1.x + o1.y * o1.y + o1.z * o1.z + o1.w * o1.w;
                #pragma unroll
                for (int o = 16; o; o >>= 1) {
                    s0 += __shfl_xor_sync(0xffffffffu, s0, o);
                    s1 += __shfl_xor_sync(0xffffffffu, s1, o);
                }
                float i0 = 1.0f / fmaxf(sqrtf(s0), 1e-12f);
                float i1 = 1.0f / fmaxf(sqrtf(s1), 1e-12f);
                o0.x = fmaxf(o0.x * i0, 0.f); o0.y = fmaxf(o0.y * i0, 0.f);
                o0.z = fmaxf(o0.z * i0, 0.f); o0.w = fmaxf(o0.w * i0, 0.f);
                o1.x = fmaxf(o1.x * i1, 0.f); o1.y = fmaxf(o1.y * i1, 0.f);
                o1.z = fmaxf(o1.z * i1, 0.f); o1.w = fmaxf(o1.w * i1, 0.f);
            }
            *reinterpret_cast<float4*>(out + (size_t)(base + 2 * p)     * D + j0) = o0;
            *reinterpret_cast<float4*>(out + (size_t)(base + 2 * p + 1) * D + j0) = o1;
        }
    }
}

// ---------------------------------------------------------------------------
extern "C" void kernel_launch(void* const* d_in, const int* in_sizes, int n_in,
                              void* d_out, int out_size) {
    const float* x   = (const float*)d_in[0];
    const int*   ei  = (const int*)d_in[1];
    const float* W1l = (const float*)d_in[2];
    const float* b1  = (const float*)d_in[3];
    const float* W1r = (const float*)d_in[4];
    const float* W2l = (const float*)d_in[5];
    const float* b2  = (const float*)d_in[6];
    const float* W2r = (const float*)d_in[7];
    float*       out = (float*)d_out;

    const int E = in_sizes[1] / 2;

    float* hbuf = nullptr;
    cudaGetSymbolAddress((void**)&hbuf, g_h);

    int sms = 148;
    cudaDeviceGetAttribute(&sms, cudaDevAttrMultiProcessorCount, 0);

    const int smem_bytes = SAGE_SMEM_FLOATS * (int)sizeof(float);   // 229,888 B
    cudaFuncSetAttribute(sage_kernel<true>,  cudaFuncAttributeMaxDynamicSharedMemorySize, smem_bytes);
    cudaFuncSetAttribute(sage_kernel<false>, cudaFuncAttributeMaxDynamicSharedMemorySize, smem_bytes);

    const int eb = (E + 255) / 256;
    const int ab = (N_NODES + 7) / 8;

    // ---- CSR build (once per launch) ----
    detect_kernel<<<1, 1024>>>(ei);
    zero_deg_kernel<<<(N_NODES + 255) / 256, 256>>>();
    hist_kernel<<<eb, 256>>>(ei, E);
    scan_partial_kernel<<<SCAN_B, SCAN_T>>>();
    scan_part2_kernel<<<1, 128>>>(E);
    scan_final_kernel<<<SCAN_B, SCAN_T>>>();
    fill_kernel<<<eb, 256>>>(ei, E);

    // ---- Layer 1 ----
    agg_kernel<<<ab, 256>>>(x);
    sage_kernel<true><<<sms, SAGE_T, smem_bytes>>>(x, W1l, b1, W1r, hbuf);

    // ---- Layer 2 ----
    agg_kernel<<<ab, 256>>>(hbuf);
    sage_kernel<false><<<sms, SAGE_T, smem_bytes>>>(hbuf, W2l, b2, W2r, out);
}